// round 10
// baseline (speedup 1.0000x reference)
#include <cuda_runtime.h>
#include <cstdint>

typedef unsigned int u32;
typedef unsigned long long u64;

#define S_LEN   1024
#define D_DIM   64
#define CHUNK   32
#define NCHUNK  32
#define THREADS 256

// smem layout (bytes)
//   QL persistent   [0, 16384)
//   PREV double     [16384, 53248)  buf b at 16384 + b*18432 ; rows 144B
//   RAWK            [53248, 62464)  64 rows x 144B (32 floats + pad)
//   RAWV            [62464, 71168)  32 rows x 272B (64 floats + pad)
//   CONV double     [71168, 103936) per buf: KH 4K | KL 4K | VH 4K | VL 4K
//   RINV            [103936, 104448)
// prologue overlay: QH at 16384 (dead after fragment load)
#define QL_OFF   0
#define PREV_OFF 16384
#define QH_OFF   16384
#define PREVBUF  18432
#define RAWK_OFF 53248
#define RAWV_OFF 62464
#define CONV_OFF 71168
#define RINV_OFF 103936
#define SM_TOTAL 104448

#define MPROW 144

__device__ __forceinline__ u32 smem_u32(const void* p) {
    u32 a;
    asm("{ .reg .u64 t; cvta.to.shared.u64 t, %1; cvt.u32.u64 %0, t; }"
        : "=r"(a) : "l"(p));
    return a;
}
__device__ __forceinline__ u32 swz(u32 b) { return b ^ ((b >> 3) & 0x70); }

__device__ __forceinline__ void split2(float a, float b, u32& hw, u32& lw) {
    asm("cvt.rn.bf16x2.f32 %0, %1, %2;" : "=r"(hw) : "f"(b), "f"(a));
    float af  = __uint_as_float(hw << 16);
    float bf_ = __uint_as_float(hw & 0xffff0000u);
    asm("cvt.rn.bf16x2.f32 %0, %1, %2;" : "=r"(lw) : "f"(b - bf_), "f"(a - af));
}

#define LDSM4(r0,r1,r2,r3,addr) \
    asm volatile("ldmatrix.sync.aligned.m8n8.x4.shared.b16 {%0,%1,%2,%3}, [%4];" \
        : "=r"(r0),"=r"(r1),"=r"(r2),"=r"(r3) : "r"(addr))
#define LDSM4T(r0,r1,r2,r3,addr) \
    asm volatile("ldmatrix.sync.aligned.m8n8.x4.trans.shared.b16 {%0,%1,%2,%3}, [%4];" \
        : "=r"(r0),"=r"(r1),"=r"(r2),"=r"(r3) : "r"(addr))
#define MMA(c,a0,a1,a2,a3,b0,b1) \
    asm volatile("mma.sync.aligned.m16n8k16.row.col.f32.bf16.bf16.f32 " \
        "{%0,%1,%2,%3},{%4,%5,%6,%7},{%8,%9},{%0,%1,%2,%3};" \
        : "+f"((c)[0]),"+f"((c)[1]),"+f"((c)[2]),"+f"((c)[3]) \
        : "r"(a0),"r"(a1),"r"(a2),"r"(a3),"r"(b0),"r"(b1))

#define CP16(saddr, gptr) \
    asm volatile("cp.async.cg.shared.global [%0], [%1], 16;" \
        :: "r"(saddr), "l"(gptr) : "memory")
#define CP_COMMIT() asm volatile("cp.async.commit_group;" ::: "memory")
#define CP_WAIT0()  asm volatile("cp.async.wait_group 0;" ::: "memory")
#define CP_WAIT1()  asm volatile("cp.async.wait_group 1;" ::: "memory")

__device__ __forceinline__ void stage_q(char* smem, const float* qb, int tid) {
    for (int it = tid; it < 2048; it += THREADS) {
        int r = it >> 4, d4 = it & 15;
        float4 v = *(const float4*)(qb + r * 64 + d4 * 4);
        u32 h0, l0, h1, l1;
        split2(v.x, v.y, h0, l0);
        split2(v.z, v.w, h1, l1);
        u32 o = swz((u32)(r * 128 + d4 * 8));
        *(u64*)(smem + QH_OFF + o) = ((u64)h1 << 32) | h0;
        *(u64*)(smem + QL_OFF + o) = ((u64)l1 << 32) | l0;
    }
}

// convert kv (from 4 float4 in regs) into conv buffer nb
__device__ __forceinline__ void kv_convert(char* nb, int tid,
                                           float4 ka, float4 kb,
                                           float4 v0, float4 v1) {
    const int d2 = tid >> 3, s4 = tid & 7;
    float av[4] = {ka.x, ka.y, ka.z, ka.w};
    float bv[4] = {kb.x, kb.y, kb.z, kb.w};
    #pragma unroll
    for (int j = 0; j < 4; j++) {
        u32 h, l;
        split2(av[j], bv[j], h, l);
        u32 o = swz((u32)((s4 * 4 + j) * 128 + d2 * 4));
        *(u32*)(nb + o) = h;
        *(u32*)(nb + 4096 + o) = l;
    }
    u32 h0, l0, h1, l1;
    split2(v0.x, v0.y, h0, l0);
    split2(v0.z, v0.w, h1, l1);
    u32 o = swz((u32)((tid >> 4) * 128 + (tid & 15) * 8));
    *(u64*)(nb + 8192  + o) = ((u64)h1 << 32) | h0;
    *(u64*)(nb + 12288 + o) = ((u64)l1 << 32) | l0;
    split2(v1.x, v1.y, h0, l0);
    split2(v1.z, v1.w, h1, l1);
    o = swz((u32)(((tid + 256) >> 4) * 128 + (tid & 15) * 8));
    *(u64*)(nb + 8192  + o) = ((u64)h1 << 32) | h0;
    *(u64*)(nb + 12288 + o) = ((u64)l1 << 32) | l0;
}

__global__ void __launch_bounds__(THREADS, 2)
attn_fused(const float* __restrict__ qg,    const float* __restrict__ kg,
           const float* __restrict__ vg,    const float* __restrict__ prevg,
           const float* __restrict__ maskg, const float* __restrict__ scaleg,
           float* __restrict__ outg, float* __restrict__ woutg,
           float* __restrict__ soutg)
{
    extern __shared__ char smem[];
    const u32 sb  = smem_u32(smem);
    const int tid = threadIdx.x, wid = tid >> 5, lid = tid & 31;
    const int bh  = blockIdx.x >> 3;
    const int q0  = (blockIdx.x & 7) << 7;
    const int qw  = wid << 4;

    const float sc = *scaleg;
    float* rinv = (float*)(smem + RINV_OFF);

    const float* kbh = kg + (long)bh * D_DIM * S_LEN;
    const float* vbh = vg + (long)bh * S_LEN * D_DIM;
    const float* pbh = prevg + (long)bh * S_LEN * S_LEN;

    const int cprow = tid >> 3;
    const int cpj   = tid & 7;

    // ---- prologue: Q staging + kv chunk 0 (gmem->regs->conv buf 0) ----
    stage_q(smem, qg + ((long)bh * S_LEN + q0) * D_DIM, tid);
    {
        const int d2 = tid >> 3, s4 = tid & 7;
        const float* kp = kbh + (long)(2 * d2) * S_LEN + s4 * 4;
        float4 ka = *(const float4*)kp;
        float4 kb = *(const float4*)(kp + S_LEN);
        float4 v0 = *(const float4*)(vbh + (long)(tid >> 4) * 64 + (tid & 15) * 4);
        float4 v1 = *(const float4*)(vbh + (long)((tid + 256) >> 4) * 64 + (tid & 15) * 4);
        kv_convert(smem + CONV_OFF, tid, ka, kb, v0, v1);
    }
    __syncthreads();

    // persistent q-hi fragments from QH overlay
    u32 ah[4][4];
    const u32 aq = (u32)((qw + (lid & 15)) * 128 + (lid >> 4) * 16);
    #pragma unroll
    for (int ks = 0; ks < 4; ks++)
        LDSM4(ah[ks][0], ah[ks][1], ah[ks][2], ah[ks][3],
              sb + QH_OFF + swz(aq + ks * 32));
    __syncthreads();   // QH dead -> PREV buffers usable

    // issue prev(0) into PREV buf 0  (group P0)
    {
        #pragma unroll
        for (int i = 0; i < 4; i++) {
            int r = cprow + i * 32;
            CP16(sb + PREV_OFF + (u32)(r * MPROW + cpj * 16),
                 pbh + (long)(q0 + r) * S_LEN + cpj * 4);
        }
        CP_COMMIT();
    }

    const int  rl   = lid >> 2;
    const int  cb   = 2 * (lid & 3);
    const long rglo = q0 + qw + rl;
    const long rghi = rglo + 8;

    const u32 brow = (u32)((lid & 7) + ((lid >> 4) << 3));
    const u32 bcol = (u32)(((lid >> 3) & 1) << 3);
    const u32 vrow = (u32)((lid & 7) + (((lid >> 3) & 1) << 3));
    const u32 vcol = (u32)((lid >> 4) << 3);

    float out2[8][4];
    #pragma unroll
    for (int nt = 0; nt < 8; nt++)
        { out2[nt][0]=0.f; out2[nt][1]=0.f; out2[nt][2]=0.f; out2[nt][3]=0.f; }
    float s_lo = 0.f, s_hi = 0.f;

    #pragma unroll 1
    for (int c = 0; c < NCHUNK; c++) {
        // ---- (1) raw kv cp.async for chunk c+1 (group R_{c+1}) ----
        if (c < NCHUNK - 1) {
            const long sc1 = (long)(c + 1) * CHUNK;
            #pragma unroll
            for (int i = 0; i < 2; i++) {
                int idx = tid + i * 256;
                int d = idx >> 3, s16 = idx & 7;
                CP16(sb + RAWK_OFF + (u32)(d * 144 + s16 * 16),
                     kbh + (long)d * S_LEN + sc1 + s16 * 4);
            }
            #pragma unroll
            for (int i = 0; i < 2; i++) {
                int idx = tid + i * 256;
                int r = idx >> 4, d16 = idx & 15;
                CP16(sb + RAWV_OFF + (u32)(r * 272 + d16 * 16),
                     vbh + (sc1 + r) * 64 + d16 * 4);
            }
            CP_COMMIT();
            // ---- (2) prev cp.async for chunk c+1 (group P_{c+1}) ----
            const u32 mb = sb + PREV_OFF + (u32)(((c + 1) & 1) * PREVBUF);
            const long gco = (long)(c + 1) * CHUNK + cpj * 4;
            #pragma unroll
            for (int i = 0; i < 4; i++) {
                int r = cprow + i * 32;
                CP16(mb + (u32)(r * MPROW + cpj * 16),
                     pbh + (long)(q0 + r) * S_LEN + gco);
            }
            CP_COMMIT();
        }

        const u32 kvb = sb + CONV_OFF + (u32)((c & 1) * 16384);
        const u32 kh = kvb, kl = kvb + 4096, vh = kvb + 8192, vl = kvb + 12288;

        // ---- (3) QK MMAs for chunk c ----
        float acc[4][4];
        #pragma unroll
        for (int nt = 0; nt < 4; nt++)
            { acc[nt][0]=0.f; acc[nt][1]=0.f; acc[nt][2]=0.f; acc[nt][3]=0.f; }

        #pragma unroll
        for (int ks = 0; ks < 4; ks++) {
            u32 al0, al1, al2, al3;
            LDSM4(al0, al1, al2, al3, sb + QL_OFF + swz(aq + ks * 32));
            #pragma unroll
            for (int np = 0; np < 2; np++) {
                u32 off = swz((u32)((np * 16 + brow) * 128 + (ks * 16 + bcol) * 2));
                u32 h0, h1, h2, h3, l0, l1, l2, l3;
                LDSM4(h0, h1, h2, h3, kh + off);
                LDSM4(l0, l1, l2, l3, kl + off);
                MMA(acc[2*np],   ah[ks][0],ah[ks][1],ah[ks][2],ah[ks][3], h0, h1);
                MMA(acc[2*np+1], ah[ks][0],ah[ks][1],ah[ks][2],ah[ks][3], h2, h3);
                MMA(acc[2*np],   ah[ks][0],ah[ks][1],ah[ks][2],ah[ks][3], l0, l1);
                MMA(acc[2*np+1], ah[ks][0],ah[ks][1],ah[ks][2],ah[ks][3], l2, l3);
                MMA(acc[2*np],   al0,al1,al2,al3, h0, h1);
                MMA(acc[2*np+1], al0,al1,al2,al3, h2, h3);
            }
        }

        // ---- (4) retire P_c (full-chunk distance) and R_{c+1} (QK distance) ----
        if (c < NCHUNK - 1) CP_WAIT1(); else CP_WAIT0();
        __syncthreads();

        // ---- (5) epilogue: mask direct LDG (batched) + prev smem ----
        const char* mpb  = smem + PREV_OFF + (c & 1) * PREVBUF;
        const char* pmlo = mpb + (qw + rl) * MPROW + cb * 4;
        const char* pmhi = pmlo + 8 * MPROW;
        const float* mplo = maskg + rglo * S_LEN + c * CHUNK + cb;
        const float* mphi = maskg + rghi * S_LEN + c * CHUNK + cb;
        float* splo = soutg + ((long)bh * S_LEN + rglo) * S_LEN + c * CHUNK + cb;
        float* sphi = soutg + ((long)bh * S_LEN + rghi) * S_LEN + c * CHUNK + cb;

        float2 mv[8];
        #pragma unroll
        for (int nt = 0; nt < 4; nt++) {
            mv[2*nt]   = *(const float2*)(mplo + nt * 8);
            mv[2*nt+1] = *(const float2*)(mphi + nt * 8);
        }
        #pragma unroll
        for (int nt = 0; nt < 4; nt++) {
            const int so = nt * 8;
            float2 pl = *(const float2*)(pmlo + so * 4);
            float2 ph = *(const float2*)(pmhi + so * 4);
            float x0 = acc[nt][0] * mv[2*nt].x   * sc + pl.x;
            float x1 = acc[nt][1] * mv[2*nt].y   * sc + pl.y;
            float x2 = acc[nt][2] * mv[2*nt+1].x * sc + ph.x;
            float x3 = acc[nt][3] * mv[2*nt+1].y * sc + ph.y;
            float2 olo = {x0, x1}, ohi = {x2, x3};
            *(float2*)(splo + so) = olo;
            *(float2*)(sphi + so) = ohi;
            float p0 = __expf(x0), p1 = __expf(x1);
            float p2 = __expf(x2), p3 = __expf(x3);
            acc[nt][0] = p0; acc[nt][1] = p1; acc[nt][2] = p2; acc[nt][3] = p3;
            s_lo += p0 + p1;
            s_hi += p2 + p3;
        }

        // ---- (6) convert raw kv (c+1) -> conv[(c+1)&1] ----
        if (c < NCHUNK - 1) {
            const int d2 = tid >> 3, s4 = tid & 7;
            float4 ka = *(const float4*)(smem + RAWK_OFF + (2 * d2) * 144 + s4 * 16);
            float4 kb = *(const float4*)(smem + RAWK_OFF + (2 * d2 + 1) * 144 + s4 * 16);
            float4 v0 = *(const float4*)(smem + RAWV_OFF + (tid >> 4) * 272 + (tid & 15) * 16);
            float4 v1 = *(const float4*)(smem + RAWV_OFF + ((tid >> 4) + 16) * 272 + (tid & 15) * 16);
            kv_convert(smem + CONV_OFF + ((c + 1) & 1) * 16384, tid, ka, kb, v0, v1);
        }

        // ---- (7) AV: out2 += P x V ----
        #pragma unroll
        for (int t = 0; t < 2; t++) {
            u32 a0, a1, a2, a3, e0, e1, e2, e3;
            split2(acc[2*t][0],   acc[2*t][1],   a0, e0);
            split2(acc[2*t][2],   acc[2*t][3],   a1, e1);
            split2(acc[2*t+1][0], acc[2*t+1][1], a2, e2);
            split2(acc[2*t+1][2], acc[2*t+1][3], a3, e3);
            #pragma unroll
            for (int dp = 0; dp < 4; dp++) {
                u32 off = swz((u32)((t * 16 + vrow) * 128 + (dp * 16 + vcol) * 2));
                u32 h0, h1, h2, h3, l0, l1, l2, l3;
                LDSM4T(h0, h1, h2, h3, vh + off);
                LDSM4T(l0, l1, l2, l3, vl + off);
                MMA(out2[2*dp],   a0,a1,a2,a3, h0, h1);
                MMA(out2[2*dp+1], a0,a1,a2,a3, h2, h3);
                MMA(out2[2*dp],   a0,a1,a2,a3, l0, l1);
                MMA(out2[2*dp+1], a0,a1,a2,a3, l2, l3);
                MMA(out2[2*dp],   e0,e1,e2,e3, h0, h1);
                MMA(out2[2*dp+1], e0,e1,e2,e3, h2, h3);
            }
        }
        // ---- (8) guard raw/conv/prev buffer reuse ----
        __syncthreads();
    }

    // ---- row sums -> inv ----
    s_lo += __shfl_xor_sync(0xffffffffu, s_lo, 1);
    s_lo += __shfl_xor_sync(0xffffffffu, s_lo, 2);
    s_hi += __shfl_xor_sync(0xffffffffu, s_hi, 1);
    s_hi += __shfl_xor_sync(0xffffffffu, s_hi, 2);
    if ((lid & 3) == 0) {
        rinv[qw + rl]     = 1.0f / s_lo;
        rinv[qw + rl + 8] = 1.0f / s_hi;
    }
    __syncthreads();

    // ---- output = out2 * inv ----
    {
        const float inv_lo = rinv[qw + rl];
        const float inv_hi = rinv[qw + rl + 8];
        float* olo = outg + ((long)bh * S_LEN + rglo) * D_DIM + cb;
        float* ohi = outg + ((long)bh * S_LEN + rghi) * D_DIM + cb;
        #pragma unroll
        for (int nt = 0; nt < 8; nt++) {
            float2 a = {out2[nt][0] * inv_lo, out2[nt][1] * inv_lo};
            float2 b = {out2[nt][2] * inv_hi, out2[nt][3] * inv_hi};
            __stcs((float2*)(olo + nt * 8), a);
            __stcs((float2*)(ohi + nt * 8), b);
        }
    }

    // ---- weights tail: coalesced stream, w = exp(s) * inv ----
    for (int r = 0; r < 16; r++) {
        const int row = qw + r;
        const float inv = rinv[row];
        const float* srow = soutg + ((long)bh * S_LEN + q0 + row) * S_LEN;
        float*       wrow = woutg + ((long)bh * S_LEN + q0 + row) * S_LEN;
        #pragma unroll
        for (int j = 0; j < 8; j++) {
            const int idx = j * 128 + lid * 4;
            float4 s = *(const float4*)(srow + idx);
            float4 w;
            w.x = __expf(s.x) * inv;
            w.y = __expf(s.y) * inv;
            w.z = __expf(s.z) * inv;
            w.w = __expf(s.w) * inv;
            __stcs((float4*)(wrow + idx), w);
        }
    }
}

extern "C" void kernel_launch(void* const* d_in, const int* in_sizes, int n_in,
                              void* d_out, int out_size) {
    const float* q     = (const float*)d_in[0];
    const float* k     = (const float*)d_in[1];
    const float* v     = (const float*)d_in[2];
    const float* prev  = (const float*)d_in[3];
    const float* mask  = (const float*)d_in[4];
    const float* scale = (const float*)d_in[5];

    float* out  = (float*)d_out;
    float* wout = out  + (long)8 * 16 * 1024 * 64;
    float* sout = wout + (long)8 * 16 * 1024 * 1024;

    cudaFuncSetAttribute(attn_fused,
                         cudaFuncAttributeMaxDynamicSharedMemorySize, SM_TOTAL);
    attn_fused<<<8 * 16 * 8, THREADS, SM_TOTAL>>>(
        q, k, v, prev, mask, scale, out, wout, sout);
}

// round 11
// speedup vs baseline: 1.5466x; 1.5466x over previous
#include <cuda_runtime.h>
#include <cstdint>

typedef unsigned int u32;
typedef unsigned long long u64;

#define S_LEN   1024
#define D_DIM   64
#define CHUNK   32
#define NCHUNK  32
#define THREADS 256

// smem layout (bytes)
//   MP double buffer [0, 65536): buf b at b*32768 (PREV 16K | MASK 16K), SW128-swizzled
//   KV buffers       [65536, 98304): per buf KH|KL|VH|VL 4K each
//   SCORE tile       [98304, 114688): 128 x 128B SW128-swizzled (RINV overlays after last flush)
// prologue overlay: QH at 0, QL at 16384 (inside MP buf 0; dead before prev(0) lands)
#define QH_OFF    0
#define QL_OFF    16384
#define MP_OFF    0
#define MPBUF     32768
#define KV_OFF    65536
#define SCORE_OFF 98304
#define RINV_OFF  98304
#define SM_TOTAL  114688

__device__ __forceinline__ u32 smem_u32(const void* p) {
    u32 a;
    asm("{ .reg .u64 t; cvta.to.shared.u64 t, %1; cvt.u32.u64 %0, t; }"
        : "=r"(a) : "l"(p));
    return a;
}
__device__ __forceinline__ u32 swz(u32 b) { return b ^ ((b >> 3) & 0x70); }

__device__ __forceinline__ void split2(float a, float b, u32& hw, u32& lw) {
    asm("cvt.rn.bf16x2.f32 %0, %1, %2;" : "=r"(hw) : "f"(b), "f"(a));
    float af  = __uint_as_float(hw << 16);
    float bf_ = __uint_as_float(hw & 0xffff0000u);
    asm("cvt.rn.bf16x2.f32 %0, %1, %2;" : "=r"(lw) : "f"(b - bf_), "f"(a - af));
}

#define LDSM4(r0,r1,r2,r3,addr) \
    asm volatile("ldmatrix.sync.aligned.m8n8.x4.shared.b16 {%0,%1,%2,%3}, [%4];" \
        : "=r"(r0),"=r"(r1),"=r"(r2),"=r"(r3) : "r"(addr))
#define LDSM4T(r0,r1,r2,r3,addr) \
    asm volatile("ldmatrix.sync.aligned.m8n8.x4.trans.shared.b16 {%0,%1,%2,%3}, [%4];" \
        : "=r"(r0),"=r"(r1),"=r"(r2),"=r"(r3) : "r"(addr))
#define MMA(c,a0,a1,a2,a3,b0,b1) \
    asm volatile("mma.sync.aligned.m16n8k16.row.col.f32.bf16.bf16.f32 " \
        "{%0,%1,%2,%3},{%4,%5,%6,%7},{%8,%9},{%0,%1,%2,%3};" \
        : "+f"((c)[0]),"+f"((c)[1]),"+f"((c)[2]),"+f"((c)[3]) \
        : "r"(a0),"r"(a1),"r"(a2),"r"(a3),"r"(b0),"r"(b1))

#define CP16(saddr, gptr) \
    asm volatile("cp.async.cg.shared.global [%0], [%1], 16;" \
        :: "r"(saddr), "l"(gptr) : "memory")
#define CP_COMMIT() asm volatile("cp.async.commit_group;" ::: "memory")
#define CP_WAIT0()  asm volatile("cp.async.wait_group 0;" ::: "memory")
#define CP_WAIT1()  asm volatile("cp.async.wait_group 1;" ::: "memory")

__device__ __forceinline__ void stage_q(char* smem, const float* qb, int tid) {
    for (int it = tid; it < 2048; it += THREADS) {
        int r = it >> 4, d4 = it & 15;
        float4 v = *(const float4*)(qb + r * 64 + d4 * 4);
        u32 h0, l0, h1, l1;
        split2(v.x, v.y, h0, l0);
        split2(v.z, v.w, h1, l1);
        u32 o = swz((u32)(r * 128 + d4 * 8));
        *(u64*)(smem + QH_OFF + o) = ((u64)h1 << 32) | h0;
        *(u64*)(smem + QL_OFF + o) = ((u64)l1 << 32) | l0;
    }
}

// convert one 32-s kv chunk already loaded in regs into conv buffer `nb`
__device__ __forceinline__ void kv_convert(char* nb, int tid,
                                           float4 ka, float4 kb,
                                           float4 v0, float4 v1) {
    const int d2 = tid >> 3, s4 = tid & 7;
    float av[4] = {ka.x, ka.y, ka.z, ka.w};
    float bv[4] = {kb.x, kb.y, kb.z, kb.w};
    #pragma unroll
    for (int j = 0; j < 4; j++) {
        u32 h, l;
        split2(av[j], bv[j], h, l);
        u32 o = swz((u32)((s4 * 4 + j) * 128 + d2 * 4));
        *(u32*)(nb + o) = h;
        *(u32*)(nb + 4096 + o) = l;
    }
    u32 h0, l0, h1, l1;
    split2(v0.x, v0.y, h0, l0);
    split2(v0.z, v0.w, h1, l1);
    u32 o = swz((u32)((tid >> 4) * 128 + (tid & 15) * 8));
    *(u64*)(nb + 8192  + o) = ((u64)h1 << 32) | h0;
    *(u64*)(nb + 12288 + o) = ((u64)l1 << 32) | l0;
    split2(v1.x, v1.y, h0, l0);
    split2(v1.z, v1.w, h1, l1);
    o = swz((u32)(((tid + 256) >> 4) * 128 + (tid & 15) * 8));
    *(u64*)(nb + 8192  + o) = ((u64)h1 << 32) | h0;
    *(u64*)(nb + 12288 + o) = ((u64)l1 << 32) | l0;
}

// coalesced flush of the swizzled score tile to gmem (chunk column base ccol)
__device__ __forceinline__ void flush_scores(const char* smem, float* srow_base,
                                             int ccol, int tid) {
    const int u  = tid & 7;
    const int r0 = tid >> 3;
    #pragma unroll
    for (int it = 0; it < 4; it++) {
        int r = r0 + it * 32;
        float4 sv = *(const float4*)(smem + SCORE_OFF + swz((u32)(r * 128 + u * 16)));
        *(float4*)(srow_base + (long)r * S_LEN + ccol + u * 4) = sv;
    }
}

__global__ void __launch_bounds__(THREADS, 2)
attn_fused(const float* __restrict__ qg,    const float* __restrict__ kg,
           const float* __restrict__ vg,    const float* __restrict__ prevg,
           const float* __restrict__ maskg, const float* __restrict__ scaleg,
           float* __restrict__ outg, float* __restrict__ woutg,
           float* __restrict__ soutg)
{
    extern __shared__ char smem[];
    const u32 sb  = smem_u32(smem);
    const int tid = threadIdx.x, wid = tid >> 5, lid = tid & 31;
    const int bh  = blockIdx.x >> 3;
    const int q0  = (blockIdx.x & 7) << 7;
    const int qw  = wid << 4;

    const float sc = *scaleg;
    float* rinv = (float*)(smem + RINV_OFF);

    const float* kbh = kg + (long)bh * D_DIM * S_LEN;
    const float* vbh = vg + (long)bh * S_LEN * D_DIM;
    const float* pbh = prevg + (long)bh * S_LEN * S_LEN;
    float* srow_base = soutg + ((long)bh * S_LEN + q0) * S_LEN;

    const int cprow = tid >> 3;
    const int cpj   = tid & 7;

    // ---- prologue: Q staging + kv chunk 0 ----
    stage_q(smem, qg + ((long)bh * S_LEN + q0) * D_DIM, tid);
    {
        const int d2 = tid >> 3, s4 = tid & 7;
        const float* kp = kbh + (long)(2 * d2) * S_LEN + s4 * 4;
        float4 ka = *(const float4*)kp;
        float4 kb = *(const float4*)(kp + S_LEN);
        float4 v0 = *(const float4*)(vbh + (long)(tid >> 4) * 64 + (tid & 15) * 4);
        float4 v1 = *(const float4*)(vbh + (long)((tid + 256) >> 4) * 64 + (tid & 15) * 4);
        kv_convert(smem + KV_OFF, tid, ka, kb, v0, v1);
    }
    __syncthreads();

    // persistent q fragments (hi + lo); QH/QL regions become MP buf 0 after this
    u32 ah[4][4], al[4][4];
    const u32 aq = (u32)((qw + (lid & 15)) * 128 + (lid >> 4) * 16);
    #pragma unroll
    for (int ks = 0; ks < 4; ks++) {
        LDSM4(ah[ks][0], ah[ks][1], ah[ks][2], ah[ks][3],
              sb + QH_OFF + swz(aq + ks * 32));
        LDSM4(al[ks][0], al[ks][1], al[ks][2], al[ks][3],
              sb + QL_OFF + swz(aq + ks * 32));
    }
    __syncthreads();

    // ---- issue prev+mask cp.async for chunk 0 into MP buf 0 ----
    {
        const long gco = cpj * 4;
        #pragma unroll
        for (int i = 0; i < 4; i++) {
            int r = cprow + i * 32;
            u32 o = swz((u32)(r * 128 + cpj * 16));
            CP16(sb + MP_OFF + o, pbh + (long)(q0 + r) * S_LEN + gco);
            CP16(sb + MP_OFF + 16384 + o, maskg + (long)(q0 + r) * S_LEN + gco);
        }
        CP_COMMIT();
    }

    const int  rl   = lid >> 2;
    const int  cb   = 2 * (lid & 3);
    const long rglo = q0 + qw + rl;
    const long rghi = rglo + 8;
    const int  rowLo = qw + rl;
    const int  rowHi = rowLo + 8;

    const u32 brow = (u32)((lid & 7) + ((lid >> 4) << 3));
    const u32 bcol = (u32)(((lid >> 3) & 1) << 3);
    const u32 vrow = (u32)((lid & 7) + (((lid >> 3) & 1) << 3));
    const u32 vcol = (u32)((lid >> 4) << 3);

    float out2[8][4];
    #pragma unroll
    for (int nt = 0; nt < 8; nt++)
        { out2[nt][0]=0.f; out2[nt][1]=0.f; out2[nt][2]=0.f; out2[nt][3]=0.f; }
    float s_lo = 0.f, s_hi = 0.f;

    #pragma unroll 1
    for (int c = 0; c < NCHUNK; c++) {
        // ---- (0) coalesced flush of previous chunk's score tile ----
        if (c > 0)
            flush_scores(smem, srow_base, (c - 1) * CHUNK, tid);

        // ---- (1) cp.async prev+mask for chunk c+1 into the other MP buffer ----
        if (c < NCHUNK - 1) {
            const u32 mb = sb + MP_OFF + (u32)(((c + 1) & 1) * MPBUF);
            const long gco = (long)(c + 1) * CHUNK + cpj * 4;
            #pragma unroll
            for (int i = 0; i < 4; i++) {
                int r = cprow + i * 32;
                u32 o = swz((u32)(r * 128 + cpj * 16));
                CP16(mb + o, pbh + (long)(q0 + r) * S_LEN + gco);
                CP16(mb + 16384 + o, maskg + (long)(q0 + r) * S_LEN + gco);
            }
            CP_COMMIT();
        }

        // ---- (2) kv gmem loads for chunk c+1 (regs; overlap with QK) ----
        float4 ka, kb, v0, v1;
        const int d2 = tid >> 3, s4 = tid & 7;
        if (c < NCHUNK - 1) {
            const float* kp = kbh + (long)(2 * d2) * S_LEN + (c + 1) * CHUNK + s4 * 4;
            ka = *(const float4*)kp;
            kb = *(const float4*)(kp + S_LEN);
            const float* vp = vbh + (long)((c + 1) * CHUNK) * 64;
            v0 = *(const float4*)(vp + (long)(tid >> 4) * 64 + (tid & 15) * 4);
            v1 = *(const float4*)(vp + (long)((tid + 256) >> 4) * 64 + (tid & 15) * 4);
        }

        const u32 kvb = sb + KV_OFF + (u32)((c & 1) * 16384);
        const u32 kh = kvb, kl = kvb + 4096, vh = kvb + 8192, vl = kvb + 12288;

        // ---- (3) QK MMAs for chunk c ----
        float acc[4][4];
        #pragma unroll
        for (int nt = 0; nt < 4; nt++)
            { acc[nt][0]=0.f; acc[nt][1]=0.f; acc[nt][2]=0.f; acc[nt][3]=0.f; }

        #pragma unroll
        for (int ks = 0; ks < 4; ks++) {
            #pragma unroll
            for (int np = 0; np < 2; np++) {
                u32 off = swz((u32)((np * 16 + brow) * 128 + (ks * 16 + bcol) * 2));
                u32 h0, h1, h2, h3, l0, l1, l2, l3;
                LDSM4(h0, h1, h2, h3, kh + off);
                LDSM4(l0, l1, l2, l3, kl + off);
                MMA(acc[2*np],   ah[ks][0],ah[ks][1],ah[ks][2],ah[ks][3], h0, h1);
                MMA(acc[2*np+1], ah[ks][0],ah[ks][1],ah[ks][2],ah[ks][3], h2, h3);
                MMA(acc[2*np],   ah[ks][0],ah[ks][1],ah[ks][2],ah[ks][3], l0, l1);
                MMA(acc[2*np+1], ah[ks][0],ah[ks][1],ah[ks][2],ah[ks][3], l2, l3);
                MMA(acc[2*np],   al[ks][0],al[ks][1],al[ks][2],al[ks][3], h0, h1);
                MMA(acc[2*np+1], al[ks][0],al[ks][1],al[ks][2],al[ks][3], h2, h3);
            }
        }

        // ---- (4) kv split + store for chunk c+1 (other buffer) ----
        if (c < NCHUNK - 1)
            kv_convert(smem + KV_OFF + ((c + 1) & 1) * 16384, tid, ka, kb, v0, v1);

        // ---- (5) retire chunk-c MP group (committed one chunk ago) ----
        if (c < NCHUNK - 1) CP_WAIT1(); else CP_WAIT0();
        __syncthreads();

        // ---- (6) epilogue: s = a*mask*sc + prev; STS scores (swizzled); p = exp(s) ----
        const char* mpb = smem + MP_OFF + (c & 1) * MPBUF;
        #pragma unroll
        for (int nt = 0; nt < 4; nt++) {
            const u32 offL = swz((u32)(rowLo * 128 + nt * 32 + cb * 4));
            const u32 offH = swz((u32)(rowHi * 128 + nt * 32 + cb * 4));
            float2 pl = *(const float2*)(mpb + offL);
            float2 ph = *(const float2*)(mpb + offH);
            float2 ml = *(const float2*)(mpb + 16384 + offL);
            float2 mh = *(const float2*)(mpb + 16384 + offH);
            float x0 = acc[nt][0] * ml.x * sc + pl.x;
            float x1 = acc[nt][1] * ml.y * sc + pl.y;
            float x2 = acc[nt][2] * mh.x * sc + ph.x;
            float x3 = acc[nt][3] * mh.y * sc + ph.y;
            float2 olo = {x0, x1}, ohi = {x2, x3};
            *(float2*)(smem + SCORE_OFF + offL) = olo;
            *(float2*)(smem + SCORE_OFF + offH) = ohi;
            float p0 = __expf(x0), p1 = __expf(x1);
            float p2 = __expf(x2), p3 = __expf(x3);
            acc[nt][0] = p0; acc[nt][1] = p1; acc[nt][2] = p2; acc[nt][3] = p3;
            s_lo += p0 + p1;
            s_hi += p2 + p3;
        }

        // ---- (7) AV: out2 += P x V ----
        #pragma unroll
        for (int t = 0; t < 2; t++) {
            u32 a0, a1, a2, a3, e0, e1, e2, e3;
            split2(acc[2*t][0],   acc[2*t][1],   a0, e0);
            split2(acc[2*t][2],   acc[2*t][3],   a1, e1);
            split2(acc[2*t+1][0], acc[2*t+1][1], a2, e2);
            split2(acc[2*t+1][2], acc[2*t+1][3], a3, e3);
            #pragma unroll
            for (int dp = 0; dp < 4; dp++) {
                u32 off = swz((u32)((t * 16 + vrow) * 128 + (dp * 16 + vcol) * 2));
                u32 h0, h1, h2, h3, l0, l1, l2, l3;
                LDSM4T(h0, h1, h2, h3, vh + off);
                LDSM4T(l0, l1, l2, l3, vl + off);
                MMA(out2[2*dp],   a0,a1,a2,a3, h0, h1);
                MMA(out2[2*dp+1], a0,a1,a2,a3, h2, h3);
                MMA(out2[2*dp],   a0,a1,a2,a3, l0, l1);
                MMA(out2[2*dp+1], a0,a1,a2,a3, l2, l3);
                MMA(out2[2*dp],   e0,e1,e2,e3, h0, h1);
                MMA(out2[2*dp+1], e0,e1,e2,e3, h2, h3);
            }
        }
        // ---- (8) guard MP/kv/score buffer reuse ----
        __syncthreads();
    }

    // ---- final score-tile flush ----
    flush_scores(smem, srow_base, (NCHUNK - 1) * CHUNK, tid);
    __syncthreads();   // flush reads done before RINV overlays SCORE region

    // ---- row sums -> inv ----
    s_lo += __shfl_xor_sync(0xffffffffu, s_lo, 1);
    s_lo += __shfl_xor_sync(0xffffffffu, s_lo, 2);
    s_hi += __shfl_xor_sync(0xffffffffu, s_hi, 1);
    s_hi += __shfl_xor_sync(0xffffffffu, s_hi, 2);
    if ((lid & 3) == 0) {
        rinv[rowLo] = 1.0f / s_lo;
        rinv[rowHi] = 1.0f / s_hi;
    }
    __syncthreads();

    // ---- output = out2 * inv ----
    {
        const float inv_lo = rinv[rowLo];
        const float inv_hi = rinv[rowHi];
        float* olo = outg + ((long)bh * S_LEN + rglo) * D_DIM + cb;
        float* ohi = outg + ((long)bh * S_LEN + rghi) * D_DIM + cb;
        #pragma unroll
        for (int nt = 0; nt < 8; nt++) {
            float2 a = {out2[nt][0] * inv_lo, out2[nt][1] * inv_lo};
            float2 b = {out2[nt][2] * inv_hi, out2[nt][3] * inv_hi};
            __stcs((float2*)(olo + nt * 8), a);
            __stcs((float2*)(ohi + nt * 8), b);
        }
    }

    // ---- weights tail: coalesced stream, w = exp(s) * inv ----
    for (int r = 0; r < 16; r++) {
        const int row = qw + r;
        const float inv = rinv[row];
        const float* srow = srow_base + (long)row * S_LEN;
        float*       wrow = woutg + ((long)bh * S_LEN + q0 + row) * S_LEN;
        #pragma unroll
        for (int j = 0; j < 8; j++) {
            const int idx = j * 128 + lid * 4;
            float4 s = *(const float4*)(srow + idx);
            float4 w;
            w.x = __expf(s.x) * inv;
            w.y = __expf(s.y) * inv;
            w.z = __expf(s.z) * inv;
            w.w = __expf(s.w) * inv;
            __stcs((float4*)(wrow + idx), w);
        }
    }
}

extern "C" void kernel_launch(void* const* d_in, const int* in_sizes, int n_in,
                              void* d_out, int out_size) {
    const float* q     = (const float*)d_in[0];
    const float* k     = (const float*)d_in[1];
    const float* v     = (const float*)d_in[2];
    const float* prev  = (const float*)d_in[3];
    const float* mask  = (const float*)d_in[4];
    const float* scale = (const float*)d_in[5];

    float* out  = (float*)d_out;
    float* wout = out  + (long)8 * 16 * 1024 * 64;
    float* sout = wout + (long)8 * 16 * 1024 * 1024;

    cudaFuncSetAttribute(attn_fused,
                         cudaFuncAttributeMaxDynamicSharedMemorySize, SM_TOTAL);
    attn_fused<<<8 * 16 * 8, THREADS, SM_TOTAL>>>(
        q, k, v, prev, mask, scale, out, wout, sout);
}

// round 13
// speedup vs baseline: 1.8802x; 1.2157x over previous
#include <cuda_runtime.h>
#include <cstdint>

typedef unsigned int u32;
typedef unsigned long long u64;

#define S_LEN   1024
#define D_DIM   64
#define CHUNK   32
#define NCHUNK  32
#define THREADS 256

__device__ float g_rinv[131072];   // [bh*1024 + row] = 1/rowsum

__device__ __forceinline__ u32 smem_u32(const void* p) {
    u32 a;
    asm("{ .reg .u64 t; cvta.to.shared.u64 t, %1; cvt.u32.u64 %0, t; }"
        : "=r"(a) : "l"(p));
    return a;
}
__device__ __forceinline__ u32 swz(u32 b) { return b ^ ((b >> 3) & 0x70); }

__device__ __forceinline__ void split2(float a, float b, u32& hw, u32& lw) {
    asm("cvt.rn.bf16x2.f32 %0, %1, %2;" : "=r"(hw) : "f"(b), "f"(a));
    float af  = __uint_as_float(hw << 16);
    float bf_ = __uint_as_float(hw & 0xffff0000u);
    asm("cvt.rn.bf16x2.f32 %0, %1, %2;" : "=r"(lw) : "f"(b - bf_), "f"(a - af));
}

#define LDSM4(r0,r1,r2,r3,addr) \
    asm volatile("ldmatrix.sync.aligned.m8n8.x4.shared.b16 {%0,%1,%2,%3}, [%4];" \
        : "=r"(r0),"=r"(r1),"=r"(r2),"=r"(r3) : "r"(addr))
#define LDSM4T(r0,r1,r2,r3,addr) \
    asm volatile("ldmatrix.sync.aligned.m8n8.x4.trans.shared.b16 {%0,%1,%2,%3}, [%4];" \
        : "=r"(r0),"=r"(r1),"=r"(r2),"=r"(r3) : "r"(addr))
#define MMA(c,a0,a1,a2,a3,b0,b1) \
    asm volatile("mma.sync.aligned.m16n8k16.row.col.f32.bf16.bf16.f32 " \
        "{%0,%1,%2,%3},{%4,%5,%6,%7},{%8,%9},{%0,%1,%2,%3};" \
        : "+f"((c)[0]),"+f"((c)[1]),"+f"((c)[2]),"+f"((c)[3]) \
        : "r"(a0),"r"(a1),"r"(a2),"r"(a3),"r"(b0),"r"(b1))

#define CP16(saddr, gptr) \
    asm volatile("cp.async.cg.shared.global [%0], [%1], 16;" \
        :: "r"(saddr), "l"(gptr) : "memory")
#define CP_COMMIT() asm volatile("cp.async.commit_group;" ::: "memory")
#define CP_WAIT0()  asm volatile("cp.async.wait_group 0;" ::: "memory")
#define CP_WAIT1()  asm volatile("cp.async.wait_group 1;" ::: "memory")

// ============================================================================
// Kernel 1: QK -> scores -> row sums
// smem: PREV double [0, 32768) buf b at b*16384 (swizzled 128 x 128B)
//       KCONV double [32768, 49152): per buf KH 4K | KL 4K
// prologue overlay: QH at 0, QL at 16384
// ============================================================================
#define K1_PREV  0
#define K1_QH    0
#define K1_QL    16384
#define K1_CONV  32768
#define K1_SMEM  49152

__device__ __forceinline__ void k_convert(char* nb, int tid, float4 ka, float4 kb) {
    const int d2 = tid >> 3, s4 = tid & 7;
    float av[4] = {ka.x, ka.y, ka.z, ka.w};
    float bv[4] = {kb.x, kb.y, kb.z, kb.w};
    #pragma unroll
    for (int j = 0; j < 4; j++) {
        u32 h, l;
        split2(av[j], bv[j], h, l);
        u32 o = swz((u32)((s4 * 4 + j) * 128 + d2 * 4));
        *(u32*)(nb + o) = h;
        *(u32*)(nb + 4096 + o) = l;
    }
}

__global__ void __launch_bounds__(THREADS, 3)
qk_scores(const float* __restrict__ qg,    const float* __restrict__ kg,
          const float* __restrict__ prevg, const float* __restrict__ maskg,
          const float* __restrict__ scaleg, float* __restrict__ soutg)
{
    extern __shared__ char smem[];
    const u32 sb  = smem_u32(smem);
    const int tid = threadIdx.x, wid = tid >> 5, lid = tid & 31;
    const int bh  = blockIdx.x >> 3;
    const int q0  = (blockIdx.x & 7) << 7;
    const int qw  = wid << 4;

    const float sc = *scaleg;
    const float* kbh = kg + (long)bh * D_DIM * S_LEN;
    const float* pbh = prevg + (long)bh * S_LEN * S_LEN;

    const int cprow = tid >> 3;
    const int cpj   = tid & 7;

    // ---- prologue: Q staging + k chunk 0 convert ----
    {
        const float* qb = qg + ((long)bh * S_LEN + q0) * D_DIM;
        for (int it = tid; it < 2048; it += THREADS) {
            int r = it >> 4, d4 = it & 15;
            float4 v = *(const float4*)(qb + r * 64 + d4 * 4);
            u32 h0, l0, h1, l1;
            split2(v.x, v.y, h0, l0);
            split2(v.z, v.w, h1, l1);
            u32 o = swz((u32)(r * 128 + d4 * 8));
            *(u64*)(smem + K1_QH + o) = ((u64)h1 << 32) | h0;
            *(u64*)(smem + K1_QL + o) = ((u64)l1 << 32) | l0;
        }
        const int d2 = tid >> 3, s4 = tid & 7;
        const float* kp = kbh + (long)(2 * d2) * S_LEN + s4 * 4;
        float4 ka = *(const float4*)kp;
        float4 kb = *(const float4*)(kp + S_LEN);
        k_convert(smem + K1_CONV, tid, ka, kb);
    }
    __syncthreads();

    u32 ah[4][4], al[4][4];
    const u32 aq = (u32)((qw + (lid & 15)) * 128 + (lid >> 4) * 16);
    #pragma unroll
    for (int ks = 0; ks < 4; ks++) {
        LDSM4(ah[ks][0], ah[ks][1], ah[ks][2], ah[ks][3],
              sb + K1_QH + swz(aq + ks * 32));
        LDSM4(al[ks][0], al[ks][1], al[ks][2], al[ks][3],
              sb + K1_QL + swz(aq + ks * 32));
    }
    __syncthreads();   // QH/QL dead -> PREV buffers usable

    // issue prev(0) into buf 0
    {
        #pragma unroll
        for (int i = 0; i < 4; i++) {
            int r = cprow + i * 32;
            CP16(sb + K1_PREV + swz((u32)(r * 128 + cpj * 16)),
                 pbh + (long)(q0 + r) * S_LEN + cpj * 4);
        }
        CP_COMMIT();
    }

    const int  rl    = lid >> 2;
    const int  cb    = 2 * (lid & 3);
    const long rglo  = q0 + qw + rl;
    const long rghi  = rglo + 8;
    const int  rowLo = qw + rl;
    const int  rowHi = rowLo + 8;

    const u32 brow = (u32)((lid & 7) + ((lid >> 4) << 3));
    const u32 bcol = (u32)(((lid >> 3) & 1) << 3);

    float s_lo = 0.f, s_hi = 0.f;

    #pragma unroll 1
    for (int c = 0; c < NCHUNK; c++) {
        // (1) prev(c+1) cp.async
        if (c < NCHUNK - 1) {
            const u32 mb = sb + K1_PREV + (u32)(((c + 1) & 1) * 16384);
            const long gco = (long)(c + 1) * CHUNK + cpj * 4;
            #pragma unroll
            for (int i = 0; i < 4; i++) {
                int r = cprow + i * 32;
                CP16(mb + swz((u32)(r * 128 + cpj * 16)),
                     pbh + (long)(q0 + r) * S_LEN + gco);
            }
            CP_COMMIT();
        }

        // (2) k(c+1) loads into regs (overlap with QK)
        float4 ka, kb;
        const int d2 = tid >> 3, s4 = tid & 7;
        if (c < NCHUNK - 1) {
            const float* kp = kbh + (long)(2 * d2) * S_LEN + (c + 1) * CHUNK + s4 * 4;
            ka = *(const float4*)kp;
            kb = *(const float4*)(kp + S_LEN);
        }

        const u32 kvb = sb + K1_CONV + (u32)((c & 1) * 8192);
        const u32 kh = kvb, kl = kvb + 4096;

        // (3) QK MMAs
        float acc[4][4];
        #pragma unroll
        for (int nt = 0; nt < 4; nt++)
            { acc[nt][0]=0.f; acc[nt][1]=0.f; acc[nt][2]=0.f; acc[nt][3]=0.f; }

        #pragma unroll
        for (int ks = 0; ks < 4; ks++) {
            #pragma unroll
            for (int np = 0; np < 2; np++) {
                u32 off = swz((u32)((np * 16 + brow) * 128 + (ks * 16 + bcol) * 2));
                u32 h0, h1, h2, h3, l0, l1, l2, l3;
                LDSM4(h0, h1, h2, h3, kh + off);
                LDSM4(l0, l1, l2, l3, kl + off);
                MMA(acc[2*np],   ah[ks][0],ah[ks][1],ah[ks][2],ah[ks][3], h0, h1);
                MMA(acc[2*np+1], ah[ks][0],ah[ks][1],ah[ks][2],ah[ks][3], h2, h3);
                MMA(acc[2*np],   ah[ks][0],ah[ks][1],ah[ks][2],ah[ks][3], l0, l1);
                MMA(acc[2*np+1], ah[ks][0],ah[ks][1],ah[ks][2],ah[ks][3], l2, l3);
                MMA(acc[2*np],   al[ks][0],al[ks][1],al[ks][2],al[ks][3], h0, h1);
                MMA(acc[2*np+1], al[ks][0],al[ks][1],al[ks][2],al[ks][3], h2, h3);
            }
        }

        // (4) k convert(c+1)
        if (c < NCHUNK - 1)
            k_convert(smem + K1_CONV + ((c + 1) & 1) * 8192, tid, ka, kb);

        // (5) retire prev(c)
        if (c < NCHUNK - 1) CP_WAIT1(); else CP_WAIT0();
        __syncthreads();

        // (6) epilogue: mask direct LDG (L2-hot), prev from smem, STG scores, exp-sum
        const char* mpb = smem + K1_PREV + (c & 1) * 16384;
        const float* mplo = maskg + rglo * S_LEN + c * CHUNK + cb;
        const float* mphi = maskg + rghi * S_LEN + c * CHUNK + cb;
        float* splo = soutg + ((long)bh * S_LEN + rglo) * S_LEN + c * CHUNK + cb;
        float* sphi = soutg + ((long)bh * S_LEN + rghi) * S_LEN + c * CHUNK + cb;

        float2 mv[8];
        #pragma unroll
        for (int nt = 0; nt < 4; nt++) {
            mv[2*nt]   = *(const float2*)(mplo + nt * 8);
            mv[2*nt+1] = *(const float2*)(mphi + nt * 8);
        }
        #pragma unroll
        for (int nt = 0; nt < 4; nt++) {
            const u32 offL = swz((u32)(rowLo * 128 + nt * 32 + cb * 4));
            const u32 offH = swz((u32)(rowHi * 128 + nt * 32 + cb * 4));
            float2 pl = *(const float2*)(mpb + offL);
            float2 ph = *(const float2*)(mpb + offH);
            float x0 = acc[nt][0] * mv[2*nt].x   * sc + pl.x;
            float x1 = acc[nt][1] * mv[2*nt].y   * sc + pl.y;
            float x2 = acc[nt][2] * mv[2*nt+1].x * sc + ph.x;
            float x3 = acc[nt][3] * mv[2*nt+1].y * sc + ph.y;
            float2 olo = {x0, x1}, ohi = {x2, x3};
            __stcs((float2*)(splo + nt * 8), olo);
            __stcs((float2*)(sphi + nt * 8), ohi);
            s_lo += __expf(x0) + __expf(x1);
            s_hi += __expf(x2) + __expf(x3);
        }

        // (7) guard buffer reuse
        __syncthreads();
    }

    // row sums -> g_rinv
    s_lo += __shfl_xor_sync(0xffffffffu, s_lo, 1);
    s_lo += __shfl_xor_sync(0xffffffffu, s_lo, 2);
    s_hi += __shfl_xor_sync(0xffffffffu, s_hi, 1);
    s_hi += __shfl_xor_sync(0xffffffffu, s_hi, 2);
    if ((lid & 3) == 0) {
        g_rinv[(long)bh * S_LEN + q0 + rowLo] = 1.0f / s_lo;
        g_rinv[(long)bh * S_LEN + q0 + rowHi] = 1.0f / s_hi;
    }
}

// ============================================================================
// Kernel 2: weights stream + AV
// smem: STILE double [0, 32768) buf b at b*16384 (swizzled 128 x 128B)
//       RAWV double  [32768, 49152) buf b at 32768 + b*8192 (32 x 256B)
//       VCONV double [49152, 65536) per buf VH 4K | VL 4K
//       RINV [65536, 66048)
// ============================================================================
#define K2_STILE 0
#define K2_RAWV  32768
#define K2_VCONV 49152
#define K2_RINV  65536
#define K2_SMEM  66048

__device__ __forceinline__ void v_convert(char* smem, int tid, int buf,
                                          float4 v0, float4 v1) {
    char* nb = smem + K2_VCONV + buf * 8192;
    u32 h0, l0, h1, l1;
    split2(v0.x, v0.y, h0, l0);
    split2(v0.z, v0.w, h1, l1);
    u32 o = swz((u32)((tid >> 4) * 128 + (tid & 15) * 8));
    *(u64*)(nb + o)        = ((u64)h1 << 32) | h0;
    *(u64*)(nb + 4096 + o) = ((u64)l1 << 32) | l0;
    split2(v1.x, v1.y, h0, l0);
    split2(v1.z, v1.w, h1, l1);
    o = swz((u32)(((tid >> 4) + 16) * 128 + (tid & 15) * 8));
    *(u64*)(nb + o)        = ((u64)h1 << 32) | h0;
    *(u64*)(nb + 4096 + o) = ((u64)l1 << 32) | l0;
}

__global__ void __launch_bounds__(THREADS, 3)
av_weights(const float* __restrict__ vg, const float* __restrict__ soutg,
           float* __restrict__ outg, float* __restrict__ woutg)
{
    extern __shared__ char smem[];
    const u32 sb  = smem_u32(smem);
    const int tid = threadIdx.x, wid = tid >> 5, lid = tid & 31;
    const int bh  = blockIdx.x >> 3;
    const int q0  = (blockIdx.x & 7) << 7;
    const int qw  = wid << 4;

    float* rinv = (float*)(smem + K2_RINV);
    const float* vbh = vg + (long)bh * S_LEN * D_DIM;
    const float* srow_base = soutg + ((long)bh * S_LEN + q0) * S_LEN;
    float*       wrow_base = woutg + ((long)bh * S_LEN + q0) * S_LEN;

    // prologue: rinv, v(0) convert, scores(0) cp.async
    if (tid < 128) rinv[tid] = g_rinv[(long)bh * S_LEN + q0 + tid];
    {
        float4 v0 = *(const float4*)(vbh + (long)(tid >> 4) * 64 + (tid & 15) * 4);
        float4 v1 = *(const float4*)(vbh + (long)((tid >> 4) + 16) * 64 + (tid & 15) * 4);
        v_convert(smem, tid, 0, v0, v1);
    }
    {
        const int r0 = tid >> 3, u = tid & 7;
        #pragma unroll
        for (int i = 0; i < 4; i++) {
            int r = r0 + i * 32;   // wait: r0 in 0..31, +i*32 -> 0..127
            CP16(sb + K2_STILE + swz((u32)(r * 128 + u * 16)),
                 srow_base + (long)r * S_LEN + u * 4);
        }
        CP_COMMIT();
    }

    const int  rl    = lid >> 2;
    const int  cb    = 2 * (lid & 3);
    const int  rowLo = qw + rl;
    const int  rowHi = rowLo + 8;
    const long rglo  = q0 + rowLo;
    const long rghi  = rglo + 8;

    const u32 vrow = (u32)((lid & 7) + (((lid >> 3) & 1) << 3));
    const u32 vcol = (u32)((lid >> 4) << 3);

    float out2[8][4];
    #pragma unroll
    for (int nt = 0; nt < 8; nt++)
        { out2[nt][0]=0.f; out2[nt][1]=0.f; out2[nt][2]=0.f; out2[nt][3]=0.f; }

    __syncthreads();   // rinv + vconv(0) visible
    const float invLo = rinv[rowLo];
    const float invHi = rinv[rowHi];

    #pragma unroll 1
    for (int c = 0; c < NCHUNK; c++) {
        // (0) issue scores(c+1) + rawv(c+1) as one group
        if (c < NCHUNK - 1) {
            const u32 stb = sb + K2_STILE + (u32)(((c + 1) & 1) * 16384);
            const long gco = (long)(c + 1) * CHUNK;
            const int r0 = tid >> 3, u = tid & 7;
            #pragma unroll
            for (int i = 0; i < 4; i++) {
                int r = r0 + i * 32;
                CP16(stb + swz((u32)(r * 128 + u * 16)),
                     srow_base + (long)r * S_LEN + gco + u * 4);
            }
            const u32 rvb = sb + K2_RAWV + (u32)(((c + 1) & 1) * 8192);
            #pragma unroll
            for (int i = 0; i < 2; i++) {
                int idx = tid + i * 256;
                int r = idx >> 4, d16 = idx & 15;
                CP16(rvb + (u32)(r * 256 + d16 * 16),
                     vbh + (gco + r) * 64 + d16 * 4);
            }
            CP_COMMIT();
        }

        // (1) retire group c (issued a full chunk ago)
        if (c < NCHUNK - 1) CP_WAIT1(); else CP_WAIT0();
        __syncthreads();

        // (2) v convert for chunk c (c>=1; chunk 0 done in prologue)
        if (c > 0) {
            const char* rv = smem + K2_RAWV + (c & 1) * 8192;
            float4 v0 = *(const float4*)(rv + (tid >> 4) * 256 + (tid & 15) * 16);
            float4 v1 = *(const float4*)(rv + ((tid >> 4) + 16) * 256 + (tid & 15) * 16);
            v_convert(smem, tid, c & 1, v0, v1);
        }

        const char* st = smem + K2_STILE + (c & 1) * 16384;
        const u32 vh = sb + K2_VCONV + (u32)((c & 1) * 8192);
        const u32 vl = vh + 4096;

        // (3) fragments: w = exp(s)*inv at mma A positions
        float acc[4][4];
        #pragma unroll
        for (int nt = 0; nt < 4; nt++) {
            float2 xl = *(const float2*)(st + swz((u32)(rowLo * 128 + nt * 32 + cb * 4)));
            float2 xh = *(const float2*)(st + swz((u32)(rowHi * 128 + nt * 32 + cb * 4)));
            acc[nt][0] = __expf(xl.x) * invLo;
            acc[nt][1] = __expf(xl.y) * invLo;
            acc[nt][2] = __expf(xh.x) * invHi;
            acc[nt][3] = __expf(xh.y) * invHi;
        }

        // (4) weights stream: coalesced LDS -> exp -> STG
        {
            const int r0 = tid >> 3, u = tid & 7;
            #pragma unroll
            for (int i = 0; i < 4; i++) {
                int r = r0 + i * 32;
                float4 s = *(const float4*)(st + swz((u32)(r * 128 + u * 16)));
                const float inv = rinv[r];
                float4 w;
                w.x = __expf(s.x) * inv;
                w.y = __expf(s.y) * inv;
                w.z = __expf(s.z) * inv;
                w.w = __expf(s.w) * inv;
                __stcs((float4*)(wrow_base + (long)r * S_LEN + c * CHUNK + u * 4), w);
            }
        }

        // (5) AV: out2 += W x V  (wait for v_convert visibility first)
        __syncthreads();
        #pragma unroll
        for (int t = 0; t < 2; t++) {
            u32 a0, a1, a2, a3, e0, e1, e2, e3;
            split2(acc[2*t][0],   acc[2*t][1],   a0, e0);
            split2(acc[2*t][2],   acc[2*t][3],   a1, e1);
            split2(acc[2*t+1][0], acc[2*t+1][1], a2, e2);
            split2(acc[2*t+1][2], acc[2*t+1][3], a3, e3);
            #pragma unroll
            for (int dp = 0; dp < 4; dp++) {
                u32 off = swz((u32)((t * 16 + vrow) * 128 + (dp * 16 + vcol) * 2));
                u32 h0, h1, h2, h3, l0, l1, l2, l3;
                LDSM4T(h0, h1, h2, h3, vh + off);
                LDSM4T(l0, l1, l2, l3, vl + off);
                MMA(out2[2*dp],   a0,a1,a2,a3, h0, h1);
                MMA(out2[2*dp+1], a0,a1,a2,a3, h2, h3);
                MMA(out2[2*dp],   a0,a1,a2,a3, l0, l1);
                MMA(out2[2*dp+1], a0,a1,a2,a3, l2, l3);
                MMA(out2[2*dp],   e0,e1,e2,e3, h0, h1);
                MMA(out2[2*dp+1], e0,e1,e2,e3, h2, h3);
            }
        }
    }

    // output (pre-normalized)
    {
        float* olo = outg + ((long)bh * S_LEN + rglo) * D_DIM + cb;
        float* ohi = outg + ((long)bh * S_LEN + rghi) * D_DIM + cb;
        #pragma unroll
        for (int nt = 0; nt < 8; nt++) {
            float2 a = {out2[nt][0], out2[nt][1]};
            float2 b = {out2[nt][2], out2[nt][3]};
            __stcs((float2*)(olo + nt * 8), a);
            __stcs((float2*)(ohi + nt * 8), b);
        }
    }
}

extern "C" void kernel_launch(void* const* d_in, const int* in_sizes, int n_in,
                              void* d_out, int out_size) {
    const float* q     = (const float*)d_in[0];
    const float* k     = (const float*)d_in[1];
    const float* v     = (const float*)d_in[2];
    const float* prev  = (const float*)d_in[3];
    const float* mask  = (const float*)d_in[4];
    const float* scale = (const float*)d_in[5];

    float* out  = (float*)d_out;
    float* wout = out  + (long)8 * 16 * 1024 * 64;
    float* sout = wout + (long)8 * 16 * 1024 * 1024;

    cudaFuncSetAttribute(qk_scores,
                         cudaFuncAttributeMaxDynamicSharedMemorySize, K1_SMEM);
    cudaFuncSetAttribute(av_weights,
                         cudaFuncAttributeMaxDynamicSharedMemorySize, K2_SMEM);
    qk_scores<<<8 * 16 * 8, THREADS, K1_SMEM>>>(q, k, prev, mask, scale, sout);
    av_weights<<<8 * 16 * 8, THREADS, K2_SMEM>>>(v, sout, out, wout);
}